// round 1
// baseline (speedup 1.0000x reference)
#include <cuda_runtime.h>

// GRU: B=256, T=2048, I=10, H=64. PyTorch gate order (r, z, n).
// One CTA per batch-pair (packed f32x2 lanes = batch0/batch1).
// 192 threads = (gate 0..2) x (unit 0..63). W_hh rows live in registers,
// duplicated across both f32x2 lanes. h broadcast from shared.

#define B_    256
#define T_    2048
#define I_    10
#define H_    64
#define CHUNK 128
#define TPB   192

typedef unsigned long long ull;

__device__ __forceinline__ ull ffma2(ull a, ull b, ull c) {
    ull d;
    asm("fma.rn.f32x2 %0, %1, %2, %3;" : "=l"(d) : "l"(a), "l"(b), "l"(c));
    return d;
}
__device__ __forceinline__ ull fadd2(ull a, ull b) {
    ull d;
    asm("add.rn.f32x2 %0, %1, %2;" : "=l"(d) : "l"(a), "l"(b));
    return d;
}
__device__ __forceinline__ ull pack2(float x, float y) {
    ull d;
    asm("mov.b64 %0, {%1, %2};" : "=l"(d) : "f"(x), "f"(y));
    return d;
}
__device__ __forceinline__ void unpack2(ull a, float& x, float& y) {
    asm("mov.b64 {%0, %1}, %2;" : "=f"(x), "=f"(y) : "l"(a));
}

__device__ __forceinline__ float sigmoid_f(float x) {
    // |pre-activation| is bounded (~<10) for this problem; no overflow risk.
    return 1.0f / (1.0f + __expf(-x));
}
__device__ __forceinline__ float tanh_f(float x) {
    // Stable: e in (0,1], no overflow for any x.
    float e = __expf(-2.0f * fabsf(x));
    float t = __fdividef(1.0f - e, 1.0f + e);
    return copysignf(t, x);
}

__global__ void __launch_bounds__(TPB, 1)
gru_kernel(const float* __restrict__ noise,
           const float* __restrict__ w_ih,
           const float* __restrict__ w_hh,
           const float* __restrict__ b_ih,
           const float* __restrict__ b_hh,
           float* __restrict__ out)
{
    __shared__ __align__(16) ull sh_h[H_];          // packed h (b0, b1)
    __shared__ __align__(16) ull sh_r[H_];          // packed r gate
    __shared__ __align__(16) ull sh_z[H_];          // packed z gate
    __shared__ __align__(16) ull sh_x[CHUNK][I_];   // packed x chunk

    const int tid = threadIdx.x;
    const int g   = tid / H_;      // 0=r, 1=z, 2=n
    const int j   = tid % H_;      // hidden unit
    const int b0  = blockIdx.x * 2;

    const int row = g * H_ + j;

    // Preload this thread's weights, duplicated into both f32x2 lanes.
    ull whh[H_];
#pragma unroll
    for (int k = 0; k < H_; k++) {
        float w = w_hh[row * H_ + k];
        whh[k] = pack2(w, w);
    }
    ull wih[I_];
#pragma unroll
    for (int i = 0; i < I_; i++) {
        float w = w_ih[row * I_ + i];
        wih[i] = pack2(w, w);
    }
    const float bi = b_ih[row];
    const float bh = b_hh[row];
    const ull bi2 = pack2(bi, bi);
    const ull bh2 = pack2(bh, bh);

    if (tid < H_) sh_h[tid] = 0ull;
    __syncthreads();

    const float* xb0 = noise + (size_t)b0 * T_ * I_;   // batch b0 stream
    const float* xb1 = xb0 + (size_t)T_ * I_;          // batch b0+1 stream
    float* out0 = out + (size_t)b0 * T_ * H_;
    float* out1 = out0 + (size_t)T_ * H_;

    for (int t0 = 0; t0 < T_; t0 += CHUNK) {
        // Cooperative, fully-contiguous x chunk load (prev step's barrier
        // guarantees all reads of the old chunk are done).
        for (int idx = tid; idx < CHUNK * I_; idx += TPB) {
            float x0 = xb0[t0 * I_ + idx];
            float x1 = xb1[t0 * I_ + idx];
            sh_x[idx / I_][idx % I_] = pack2(x0, x1);
        }
        __syncthreads();

        for (int tl = 0; tl < CHUNK; tl++) {
            // ---- input projection: gi = W_ih x + b_ih ----
            ull gi = bi2;
            const ulonglong2* X2 = (const ulonglong2*)&sh_x[tl][0];
#pragma unroll
            for (int p = 0; p < I_ / 2; p++) {
                ulonglong2 xp = X2[p];
                gi = ffma2(xp.x, wih[2 * p], gi);
                gi = ffma2(xp.y, wih[2 * p + 1], gi);
            }

            // ---- hidden matvec: hv = W_hh h + b_hh ----
            ull a0 = bh2, a1 = 0ull, a2 = 0ull, a3 = 0ull;
            const ulonglong2* H4 = (const ulonglong2*)sh_h;
#pragma unroll
            for (int m = 0; m < H_ / 2; m++) {
                ulonglong2 hp = H4[m];
                if ((m & 1) == 0) {
                    a0 = ffma2(hp.x, whh[2 * m], a0);
                    a1 = ffma2(hp.y, whh[2 * m + 1], a1);
                } else {
                    a2 = ffma2(hp.x, whh[2 * m], a2);
                    a3 = ffma2(hp.y, whh[2 * m + 1], a3);
                }
            }
            ull hv = fadd2(fadd2(a0, a1), fadd2(a2, a3));

            if (g == 0) {
                float x, y;
                unpack2(fadd2(gi, hv), x, y);
                sh_r[j] = pack2(sigmoid_f(x), sigmoid_f(y));
            } else if (g == 1) {
                float x, y;
                unpack2(fadd2(gi, hv), x, y);
                sh_z[j] = pack2(sigmoid_f(x), sigmoid_f(y));
            }
            __syncthreads();

            if (g == 2) {
                float rx, ry, zx, zy, hx, hy, gx, gy, vx, vy;
                unpack2(sh_r[j], rx, ry);
                unpack2(sh_z[j], zx, zy);
                unpack2(sh_h[j], hx, hy);
                unpack2(gi, gx, gy);
                unpack2(hv, vx, vy);   // hv already includes b_hh_n (inside r*(...))
                float nx = tanh_f(fmaf(rx, vx, gx));
                float ny = tanh_f(fmaf(ry, vy, gy));
                float h0n = fmaf(zx, hx - nx, nx);   // (1-z)*n + z*h
                float h1n = fmaf(zy, hy - ny, ny);
                sh_h[j] = pack2(h0n, h1n);
                const int t = t0 + tl;
                out0[(size_t)t * H_ + j] = h0n;
                out1[(size_t)t * H_ + j] = h1n;
            }
            __syncthreads();
        }
    }
}

extern "C" void kernel_launch(void* const* d_in, const int* in_sizes, int n_in,
                              void* d_out, int out_size)
{
    const float* noise = (const float*)d_in[0];
    const float* w_ih  = (const float*)d_in[1];
    const float* w_hh  = (const float*)d_in[2];
    const float* b_ih  = (const float*)d_in[3];
    const float* b_hh  = (const float*)d_in[4];
    float* out = (float*)d_out;
    gru_kernel<<<B_ / 2, TPB>>>(noise, w_ih, w_hh, b_ih, b_hh, out);
}

// round 2
// speedup vs baseline: 1.2006x; 1.2006x over previous
#include <cuda_runtime.h>

// GRU: B=256, T=2048, I=10, H=64. PyTorch gate order (r, z, n).
// grid=128 CTAs, 384 threads each = TWO independent 192-thread streams,
// each stream = ONE batch. f32x2 packs adjacent k-pairs within the batch
// (weights (w_2k,w_2k+1), h (h_2k,h_2k+1)); one cross-lane add at the end.
// Streams sync only via their own named barriers, so two independent
// dependency chains interleave per SM and hide each other's latency.

#define B_    256
#define T_    2048
#define I_    10
#define H_    64
#define CHUNK 128
#define TPB   384
#define STPB  192   // threads per stream

typedef unsigned long long ull;

__device__ __forceinline__ ull ffma2(ull a, ull b, ull c) {
    ull d;
    asm("fma.rn.f32x2 %0, %1, %2, %3;" : "=l"(d) : "l"(a), "l"(b), "l"(c));
    return d;
}
__device__ __forceinline__ ull fadd2(ull a, ull b) {
    ull d;
    asm("add.rn.f32x2 %0, %1, %2;" : "=l"(d) : "l"(a), "l"(b));
    return d;
}
__device__ __forceinline__ ull pack2(float x, float y) {
    ull d;
    asm("mov.b64 %0, {%1, %2};" : "=l"(d) : "f"(x), "f"(y));
    return d;
}
__device__ __forceinline__ void unpack2(ull a, float& x, float& y) {
    asm("mov.b64 {%0, %1}, %2;" : "=f"(x), "=f"(y) : "l"(a));
}

__device__ __forceinline__ void bar_sync(int id) {
    asm volatile("bar.sync %0, %1;" :: "r"(id), "r"(STPB) : "memory");
}
__device__ __forceinline__ void bar_arrive(int id) {
    asm volatile("bar.arrive %0, %1;" :: "r"(id), "r"(STPB) : "memory");
}

__device__ __forceinline__ float sigmoid_f(float x) {
    return 1.0f / (1.0f + __expf(-x));
}
__device__ __forceinline__ float tanh_f(float x) {
    float e = __expf(-2.0f * fabsf(x));
    float t = __fdividef(1.0f - e, 1.0f + e);
    return copysignf(t, x);
}

__global__ void __launch_bounds__(TPB, 1)
gru_kernel(const float* __restrict__ noise,
           const float* __restrict__ w_ih,
           const float* __restrict__ w_hh,
           const float* __restrict__ b_ih,
           const float* __restrict__ b_hh,
           float* __restrict__ out)
{
    __shared__ __align__(16) float sh_h[2][H_];
    __shared__ __align__(16) float sh_r[2][H_];
    __shared__ __align__(16) float sh_z[2][H_];
    __shared__ __align__(16) float sh_x[2][CHUNK * I_];

    const int tid = threadIdx.x;
    const int s   = tid / STPB;       // stream 0/1
    const int ts  = tid % STPB;       // thread-in-stream
    const int g   = ts / H_;          // 0=r, 1=z, 2=n
    const int j   = ts % H_;          // hidden unit
    const int b   = blockIdx.x * 2 + s;
    const int row = g * H_ + j;

    const int B1 = 1 + 2 * s;         // producer barrier (r/z -> n)
    const int B2 = 2 + 2 * s;         // h-ready barrier

    // Weights packed by adjacent k-pairs (lanes share the batch).
    ull whh[H_ / 2];
#pragma unroll
    for (int m = 0; m < H_ / 2; m++)
        whh[m] = pack2(w_hh[row * H_ + 2 * m], w_hh[row * H_ + 2 * m + 1]);
    ull wih[I_ / 2];
#pragma unroll
    for (int p = 0; p < I_ / 2; p++)
        wih[p] = pack2(w_ih[row * I_ + 2 * p], w_ih[row * I_ + 2 * p + 1]);
    const float bi = b_ih[row];
    const float bh = b_hh[row];

    if (ts < H_) sh_h[s][ts] = 0.0f;
    __syncthreads();

    const float* xb = noise + (size_t)b * T_ * I_;
    float* ob = out + (size_t)b * T_ * H_;

    for (int t0 = 0; t0 < T_; t0 += CHUNK) {
        // Cooperative contiguous chunk load for this stream's batch.
        for (int idx = ts; idx < CHUNK * I_; idx += STPB)
            sh_x[s][idx] = xb[t0 * I_ + idx];
        bar_sync(B1);

        for (int tl = 0; tl < CHUNK; tl++) {
            // ---- input projection (pairs are naturally adjacent floats) ----
            const ull* xp = (const ull*)&sh_x[s][tl * I_];   // 8B-aligned (40B rows)
            ull ga = 0ull;
#pragma unroll
            for (int p = 0; p < I_ / 2; p++)
                ga = ffma2(xp[p], wih[p], ga);

            // ---- hidden matvec over k-pairs, 4 accumulators ----
            const ulonglong2* hp = (const ulonglong2*)sh_h[s];
            ull a0 = 0ull, a1 = 0ull, a2 = 0ull, a3 = 0ull;
#pragma unroll
            for (int m = 0; m < H_ / 4; m++) {
                ulonglong2 hq = hp[m];
                if ((m & 1) == 0) {
                    a0 = ffma2(hq.x, whh[2 * m], a0);
                    a1 = ffma2(hq.y, whh[2 * m + 1], a1);
                } else {
                    a2 = ffma2(hq.x, whh[2 * m], a2);
                    a3 = ffma2(hq.y, whh[2 * m + 1], a3);
                }
            }
            ull asum = fadd2(fadd2(a0, a1), fadd2(a2, a3));
            float hx, hy, gx, gy;
            unpack2(asum, hx, hy);
            unpack2(ga, gx, gy);
            const float hv  = hx + hy;       // W_hh[row] . h
            const float gis = gx + gy + bi;  // W_ih[row] . x + b_ih

            if (g < 2) {
                float act = sigmoid_f(gis + hv + bh);
                if (g == 0) sh_r[s][j] = act;
                else        sh_z[s][j] = act;
                bar_arrive(B1);              // non-blocking hand-off to n-threads
                bar_sync(B2);                // wait for new h
            } else {
                bar_sync(B1);                // wait for r, z
                const float r = sh_r[s][j];
                const float z = sh_z[s][j];
                const float hprev = sh_h[s][j];
                const float n = tanh_f(fmaf(r, hv + bh, gis));
                const float hn = fmaf(z, hprev - n, n);  // (1-z)*n + z*h
                sh_h[s][j] = hn;
                ob[(size_t)(t0 + tl) * H_ + j] = hn;
                bar_sync(B2);                // publish h to whole stream
            }
        }
    }
}

extern "C" void kernel_launch(void* const* d_in, const int* in_sizes, int n_in,
                              void* d_out, int out_size)
{
    const float* noise = (const float*)d_in[0];
    const float* w_ih  = (const float*)d_in[1];
    const float* w_hh  = (const float*)d_in[2];
    const float* b_ih  = (const float*)d_in[3];
    const float* b_hh  = (const float*)d_in[4];
    float* out = (float*)d_out;
    gru_kernel<<<B_ / 2, TPB>>>(noise, w_ih, w_hh, b_ih, b_hh, out);
}

// round 3
// speedup vs baseline: 1.4095x; 1.1740x over previous
#include <cuda_runtime.h>

// GRU: B=256, T=2048, I=10, H=64. PyTorch gate order (r, z, n).
// grid=128 CTAs x 384 threads = 2 independent 192-thread streams (1 batch each),
// synced by per-stream named barriers. f32x2 packs adjacent k-pairs.
// Input projections (gi) precomputed per 64-step chunk into dynamic shared,
// so the recurrent loop body is: LDS h -> 32 ffma2 -> reduce -> MUFU act ->
// exchange -> combine -> STS h.

#define B_    256
#define T_    2048
#define I_    10
#define H_    64
#define CHUNK 64
#define NROW  192
#define TPB   384
#define STPB  192

typedef unsigned long long ull;

__device__ __forceinline__ ull ffma2(ull a, ull b, ull c) {
    ull d;
    asm("fma.rn.f32x2 %0, %1, %2, %3;" : "=l"(d) : "l"(a), "l"(b), "l"(c));
    return d;
}
__device__ __forceinline__ ull fadd2(ull a, ull b) {
    ull d;
    asm("add.rn.f32x2 %0, %1, %2;" : "=l"(d) : "l"(a), "l"(b));
    return d;
}
__device__ __forceinline__ ull pack2(float x, float y) {
    ull d;
    asm("mov.b64 %0, {%1, %2};" : "=l"(d) : "f"(x), "f"(y));
    return d;
}
__device__ __forceinline__ void unpack2(ull a, float& x, float& y) {
    asm("mov.b64 {%0, %1}, %2;" : "=f"(x), "=f"(y) : "l"(a));
}
__device__ __forceinline__ float tanha(float x) {
    float y;
    asm("tanh.approx.f32 %0, %1;" : "=f"(y) : "f"(x));
    return y;
}
__device__ __forceinline__ void bar_sync(int id) {
    asm volatile("bar.sync %0, %1;" :: "r"(id), "r"(STPB) : "memory");
}
__device__ __forceinline__ void bar_arrive(int id) {
    asm volatile("bar.arrive %0, %1;" :: "r"(id), "r"(STPB) : "memory");
}

__global__ void __launch_bounds__(TPB, 1)
gru_kernel(const float* __restrict__ noise,
           const float* __restrict__ w_ih,
           const float* __restrict__ w_hh,
           const float* __restrict__ b_ih,
           const float* __restrict__ b_hh,
           float* __restrict__ out)
{
    extern __shared__ float dyn[];
    __shared__ __align__(16) float sh_h[2][H_];
    __shared__ __align__(16) float sh_r[2][H_];
    __shared__ __align__(16) float sh_z[2][H_];

    const int tid = threadIdx.x;
    const int s   = tid / STPB;       // stream 0/1
    const int ts  = tid % STPB;
    const int g   = ts / H_;          // 0=r, 1=z, 2=n
    const int j   = ts % H_;
    const int b   = blockIdx.x * 2 + s;
    const int row = g * H_ + j;

    float* sh_gi = dyn + s * (CHUNK * NROW);                 // [CHUNK][NROW]
    float* sh_x  = dyn + 2 * (CHUNK * NROW) + s * (CHUNK * I_);

    const int B1 = 1 + 2 * s;         // chunk sync + r/z -> n handoff
    const int B2 = 2 + 2 * s;         // h publish

    // W_hh row packed by adjacent k-pairs.
    ull whh[H_ / 2];
#pragma unroll
    for (int m = 0; m < H_ / 2; m++)
        whh[m] = pack2(w_hh[row * H_ + 2 * m], w_hh[row * H_ + 2 * m + 1]);
    ull wih[I_ / 2];
#pragma unroll
    for (int p = 0; p < I_ / 2; p++)
        wih[p] = pack2(w_ih[row * I_ + 2 * p], w_ih[row * I_ + 2 * p + 1]);

    // r,z rows: fold b_hh into the precomputed gi. n row: b_hh applied to hv.
    const float bsum = b_ih[row] + (g < 2 ? b_hh[row] : 0.0f);
    const float bh_n = (g == 2) ? b_hh[row] : 0.0f;

    if (ts < H_) sh_h[s][ts] = 0.0f;
    float hloc = 0.0f;                // n-thread's own h_j

    const float* xb = noise + (size_t)b * T_ * I_;
    float* op = out + (size_t)b * T_ * H_ + j;
    __syncthreads();

    for (int t0 = 0; t0 < T_; t0 += CHUNK) {
        // Stage x chunk (contiguous).
        for (int idx = ts; idx < CHUNK * I_; idx += STPB)
            sh_x[idx] = xb[t0 * I_ + idx];
        bar_sync(B1);

        // Precompute gi for the whole chunk: gi[t][row] = W_ih[row].x(t) + biases.
        {
            const ull* xp = (const ull*)sh_x;
            float* gw = sh_gi + row;
#pragma unroll 4
            for (int tl = 0; tl < CHUNK; tl++) {
                ull ga = 0ull;
#pragma unroll
                for (int p = 0; p < I_ / 2; p++)
                    ga = ffma2(xp[tl * (I_ / 2) + p], wih[p], ga);
                float gx, gy;
                unpack2(ga, gx, gy);
                gw[tl * NROW] = gx + gy + bsum;
            }
        }
        bar_sync(B1);

        const float* gp = sh_gi + row;
        for (int tl = 0; tl < CHUNK; tl++, gp += NROW) {
            const float a = *gp;

            // hv = W_hh[row] . h
            const ulonglong2* hp = (const ulonglong2*)sh_h[s];
            ull a0 = 0ull, a1 = 0ull, a2 = 0ull, a3 = 0ull;
#pragma unroll
            for (int m = 0; m < H_ / 4; m++) {
                ulonglong2 hq = hp[m];
                if ((m & 1) == 0) {
                    a0 = ffma2(hq.x, whh[2 * m], a0);
                    a1 = ffma2(hq.y, whh[2 * m + 1], a1);
                } else {
                    a2 = ffma2(hq.x, whh[2 * m], a2);
                    a3 = ffma2(hq.y, whh[2 * m + 1], a3);
                }
            }
            ull asum = fadd2(fadd2(a0, a1), fadd2(a2, a3));
            float hx, hy;
            unpack2(asum, hx, hy);
            float hv = hx + hy;

            if (g < 2) {
                // sigmoid(x) = 0.5*tanh(x/2) + 0.5
                float act = fmaf(0.5f, tanha(0.5f * (a + hv)), 0.5f);
                if (g == 0) sh_r[s][j] = act;
                else        sh_z[s][j] = act;
                bar_arrive(B1);
                bar_sync(B2);
            } else {
                hv += bh_n;
                bar_sync(B1);
                const float r = sh_r[s][j];
                const float z = sh_z[s][j];
                const float n = tanha(fmaf(r, hv, a));
                hloc = fmaf(z, hloc - n, n);      // (1-z)*n + z*h
                sh_h[s][j] = hloc;
                *op = hloc;
                op += H_;
                bar_sync(B2);
            }
        }
    }
}

extern "C" void kernel_launch(void* const* d_in, const int* in_sizes, int n_in,
                              void* d_out, int out_size)
{
    const float* noise = (const float*)d_in[0];
    const float* w_ih  = (const float*)d_in[1];
    const float* w_hh  = (const float*)d_in[2];
    const float* b_ih  = (const float*)d_in[3];
    const float* b_hh  = (const float*)d_in[4];
    float* out = (float*)d_out;

    const int smem = (2 * CHUNK * NROW + 2 * CHUNK * I_) * (int)sizeof(float);
    cudaFuncSetAttribute(gru_kernel, cudaFuncAttributeMaxDynamicSharedMemorySize, smem);
    gru_kernel<<<B_ / 2, TPB, smem>>>(noise, w_ih, w_hh, b_ih, b_hh, out);
}